// round 13
// baseline (speedup 1.0000x reference)
#include <cuda_runtime.h>
#include <cuda_bf16.h>

#define BATCH      8192
#define IN_F       4096
#define NCHUNK     8
#define CIN        512
#define COUT       512
#define TOPK       2

// GEMM tiling
#define BM         128
#define BN         128
#define KCB        32                   // bf16 k-elems per chunk-stage
#define NKCHUNK    (CIN / KCB)          // 16
#define RS         40                   // padded bf16 row pitch (80 B)
#define RSB        (RS * 2)
#define AP         (BM * RSB)           // 10240 B per plane
#define BP         (BN * RSB)
#define STAGE      (2 * AP + 2 * BP)    // 40960 B (Ahi,Alo,Bhi,Blo)
#define DSMEM_B    (2 * STAGE)          // 81920 B -> occupancy 2

// convert grid split
#define XBLK       8192                 // 8192*256 threads = 2,097,152 float4 (full x planes)
#define WBLK       512                  // 512*256  threads = 131,072 float4 (both W chunks)

// Device-global scratch
__device__ float    g_act[NCHUNK];
__device__ unsigned g_tick;
__device__ int      g_idx[TOPK];
// pre-converted operands: x planes [8192][1024 bf16] as uint2 (8B = 4 bf16)
__device__ uint2 g_xhi[BATCH * 256];
__device__ uint2 g_xlo[BATCH * 256];
// w planes [2][512][512 bf16] as uint2
__device__ uint2 g_whi[2 * COUT * 128];
__device__ uint2 g_wlo[2 * COUT * 128];

__device__ __forceinline__ unsigned smem_u32(const void* p) {
    unsigned a;
    asm("{ .reg .u64 t; cvta.to.shared.u64 t, %1; cvt.u32.u64 %0, t; }"
        : "=r"(a) : "l"(p));
    return a;
}

#define LDSM4(r0, r1, r2, r3, addr)                                        \
    asm volatile("ldmatrix.sync.aligned.m8n8.x4.shared.b16 {%0,%1,%2,%3}, [%4];" \
        : "=r"(r0), "=r"(r1), "=r"(r2), "=r"(r3) : "r"(addr))

#define MMA16816(c, a, b)                                                  \
    asm volatile("mma.sync.aligned.m16n8k16.row.col.f32.bf16.bf16.f32 "    \
        "{%0,%1,%2,%3}, {%4,%5,%6,%7}, {%8,%9}, {%0,%1,%2,%3};"            \
        : "+f"((c)[0]), "+f"((c)[1]), "+f"((c)[2]), "+f"((c)[3])           \
        : "r"((a)[0]), "r"((a)[1]), "r"((a)[2]), "r"((a)[3]),              \
          "r"((b)[0]), "r"((b)[1]))

#define CP16(dst, src)                                                     \
    asm volatile("cp.async.cg.shared.global [%0], [%1], 16;"               \
        :: "r"(dst), "l"(src))
#define CP_COMMIT()  asm volatile("cp.async.commit_group;" ::: "memory")
#define CP_WAIT(n)   asm volatile("cp.async.wait_group %0;" :: "n"(n) : "memory")

// ---------------------------------------------------------------------------
// 1) act + finalize (ticket): per-chunk mean|x|, top-2, activities out.
// ---------------------------------------------------------------------------
__global__ __launch_bounds__(256) void act_fused_kernel(
    const float* __restrict__ x, float* __restrict__ out_act)
{
    const int c       = blockIdx.x;
    const int rowbase = blockIdx.y * 128;
    const float* base = x + (size_t)rowbase * IN_F + c * CIN;

    float s = 0.0f;
#pragma unroll 4
    for (int it = 0; it < 64; ++it) {
        int lin = it * 256 + threadIdx.x;
        int r   = lin >> 7;
        int c4  = (lin & 127) << 2;
        float4 v = *(const float4*)(base + (size_t)r * IN_F + c4);
        s += fabsf(v.x) + fabsf(v.y) + fabsf(v.z) + fabsf(v.w);
    }
#pragma unroll
    for (int off = 16; off; off >>= 1) s += __shfl_xor_sync(0xffffffffu, s, off);
    __shared__ float ws[8];
    if ((threadIdx.x & 31) == 0) ws[threadIdx.x >> 5] = s;
    __syncthreads();
    if (threadIdx.x == 0) {
        s = ws[0];
#pragma unroll
        for (int i = 1; i < 8; ++i) s += ws[i];
        atomicAdd(&g_act[c], s);
        __threadfence();
        unsigned t = atomicAdd(&g_tick, 1u);
        if (t == (unsigned)(NCHUNK * 64 - 1)) {
            const float inv = 1.0f / ((float)BATCH * (float)CIN);
            float a[NCHUNK];
#pragma unroll
            for (int i = 0; i < NCHUNK; ++i) {
                a[i] = g_act[i] * inv;
                out_act[i] = a[i];
            }
            int i0 = 0;
#pragma unroll
            for (int i = 1; i < NCHUNK; ++i) if (a[i] > a[i0]) i0 = i;
            int i1 = (i0 == 0) ? 1 : 0;
#pragma unroll
            for (int i = 0; i < NCHUNK; ++i) if (i != i0 && a[i] > a[i1]) i1 = i;
            g_idx[0] = i0;
            g_idx[1] = i1;
#pragma unroll
            for (int i = 0; i < NCHUNK; ++i) g_act[i] = 0.0f;
            g_tick = 0u;
            __threadfence();
        }
    }
}

// ---------------------------------------------------------------------------
// split a float4 into packed bf16x2 hi (truncate) and lo (rn residual)
// ---------------------------------------------------------------------------
__device__ __forceinline__ void split4(float4 v, unsigned& hi01, unsigned& hi23,
                                       unsigned& lo01, unsigned& lo23) {
    unsigned u0 = __float_as_uint(v.x);
    unsigned u1 = __float_as_uint(v.y);
    unsigned u2 = __float_as_uint(v.z);
    unsigned u3 = __float_as_uint(v.w);
    hi01 = (u0 >> 16) | (u1 & 0xFFFF0000u);
    hi23 = (u2 >> 16) | (u3 & 0xFFFF0000u);
    float l0 = v.x - __uint_as_float(u0 & 0xFFFF0000u);
    float l1 = v.y - __uint_as_float(u1 & 0xFFFF0000u);
    float l2 = v.z - __uint_as_float(u2 & 0xFFFF0000u);
    float l3 = v.w - __uint_as_float(u3 & 0xFFFF0000u);
    __nv_bfloat162 p01 = __floats2bfloat162_rn(l0, l1);
    __nv_bfloat162 p23 = __floats2bfloat162_rn(l2, l3);
    lo01 = *(unsigned*)&p01;
    lo23 = *(unsigned*)&p23;
}

// ---------------------------------------------------------------------------
// 2) convert: selected x chunks + W -> bf16 hi/lo planes.
//    blocks [0, XBLK): x part  (XBLK*256 threads covers all 8192*256 float4)
//    blocks [XBLK, XBLK+WBLK): w part
// ---------------------------------------------------------------------------
__global__ __launch_bounds__(256) void convert_kernel(
    const float* __restrict__ x, const float* __restrict__ W)
{
    if (blockIdx.x < XBLK) {
        const int e    = blockIdx.x * 256 + threadIdx.x;   // 0 .. BATCH*256-1
        const int row  = e >> 8;          // batch row (0..8191)
        const int col4 = e & 255;         // float4 within 1024-wide plane row
        const int z    = col4 >> 7;
        const int i4   = col4 & 127;
        float4 v = *(const float4*)(x + (size_t)row * IN_F + g_idx[z] * CIN + i4 * 4);
        unsigned h01, h23, l01, l23;
        split4(v, h01, h23, l01, l23);
        g_xhi[e] = make_uint2(h01, h23);
        g_xlo[e] = make_uint2(l01, l23);
    } else {
        const int e2  = (blockIdx.x - XBLK) * 256 + threadIdx.x;  // 0..131071
        const int z   = e2 >> 16;
        const int rr  = e2 & 65535;
        const int row = rr >> 7;          // cout row
        const int q   = rr & 127;
        float4 v = *(const float4*)(W + ((size_t)g_idx[z] * COUT + row) * CIN + q * 4);
        unsigned h01, h23, l01, l23;
        split4(v, h01, h23, l01, l23);
        g_whi[e2] = make_uint2(h01, h23);
        g_wlo[e2] = make_uint2(l01, l23);
    }
}

// ---------------------------------------------------------------------------
// 3) GEMM (3xBF16 split, mma.sync) on pre-converted planes + folded zeroing.
//    grid = (4, 64, 2), 256 threads, occupancy 2, 2-stage cp.async pipeline.
// ---------------------------------------------------------------------------
__global__ __launch_bounds__(256, 2) void gemm_mma_kernel(
    const float* __restrict__ bias, float* __restrict__ out)
{
    extern __shared__ char dsm[];
    const unsigned smb = smem_u32(dsm);

    const int tid  = threadIdx.x;
    const int lane = tid & 31;
    const int wid  = tid >> 5;
    const int wm   = wid & 1;             // 2 m-warps (64 rows)
    const int wn   = wid >> 1;            // 4 n-warps (32 cols)

    const int nt    = blockIdx.x;         // 0..3
    const int mt    = blockIdx.y;         // 0..63
    const int zz    = blockIdx.z;         // 0..1
    const int chunk = g_idx[zz];
    const int zslot = nt + 4 * zz;        // 0..7 -> 64-col zero slice

    int nz[6];
    {
        int s0 = g_idx[0], s1 = g_idx[1], k = 0;
#pragma unroll
        for (int i = 0; i < NCHUNK; ++i)
            if (i != s0 && i != s1) nz[k++] = i;
    }

    // global bf16 plane bases (bytes)
    const char* xh = (const char*)g_xhi + (size_t)(mt * BM) * 2048 + zz * 1024;
    const char* xl = (const char*)g_xlo + (size_t)(mt * BM) * 2048 + zz * 1024;
    const char* wh = (const char*)g_whi + (size_t)zz * COUT * 1024 + (size_t)(nt * BN) * 1024;
    const char* wl = (const char*)g_wlo + (size_t)zz * COUT * 1024 + (size_t)(nt * BN) * 1024;

    // cp.async mapping: per plane, 2 iters: row = (tid>>2)+64*it, q = tid&3
    const int crow = tid >> 2;
    const int cq   = tid & 3;

    const unsigned a_lane = (unsigned)(((lane & 7) + ((lane >> 3) & 1) * 8) * RSB
                                       + ((lane >> 4) & 1) * 16);
    const unsigned b_lane = (unsigned)((((lane >> 4) & 1) * 8 + (lane & 7)) * RSB
                                       + ((lane >> 3) & 1) * 16);

    float acc[4][4][4];
#pragma unroll
    for (int i = 0; i < 4; ++i)
#pragma unroll
        for (int j = 0; j < 4; ++j)
#pragma unroll
            for (int k = 0; k < 4; ++k) acc[i][j][k] = 0.0f;

    auto cp_chunk = [&](int c, int s) {
        const unsigned st = smb + s * STAGE;
        const int kb = c * 64;            // byte offset along k (32 bf16)
#pragma unroll
        for (int it = 0; it < 2; ++it) {
            int row = crow + it * 64;
            unsigned d = st + row * RSB + cq * 16;
            CP16(d,                xh + (size_t)row * 2048 + kb + cq * 16);
            CP16(d + AP,           xl + (size_t)row * 2048 + kb + cq * 16);
            CP16(d + 2 * AP,       wh + (size_t)row * 1024 + kb + cq * 16);
            CP16(d + 2 * AP + BP,  wl + (size_t)row * 1024 + kb + cq * 16);
        }
        CP_COMMIT();
    };

    // prologue: stages 0 and 1
    cp_chunk(0, 0);
    cp_chunk(1, 1);
    CP_WAIT(1);
    __syncthreads();

    for (int c = 0; c < NKCHUNK; ++c) {
        const int s = c & 1;

        // folded zeroing (independent STG.128, overlaps MMA)
#pragma unroll
        for (int j = 0; j < 3; ++j) {
            int e   = (c * 3 + j) * 256 + tid;
            int f4c = e & 15;
            int row = (e >> 4) & 127;
            int c6  = e >> 11;
            float4* dst = (float4*)out
                + (size_t)(mt * 128 + row) * (IN_F / 4)
                + nz[c6] * (COUT / 4) + zslot * 16 + f4c;
            *dst = make_float4(0.f, 0.f, 0.f, 0.f);
        }

        // ---- MMA over stage s ----
        const unsigned sa  = smb + s * STAGE + (unsigned)(wm * 64) * RSB;
        const unsigned sb_ = smb + s * STAGE + 2 * AP + (unsigned)(wn * 32) * RSB;
#pragma unroll
        for (int ks = 0; ks < 2; ++ks) {
            const unsigned ko = (unsigned)ks * 32;
            unsigned ah[4][4], bh[2][4], bl[2][4];
#pragma unroll
            for (int mb = 0; mb < 4; ++mb)
                LDSM4(ah[mb][0], ah[mb][1], ah[mb][2], ah[mb][3],
                      sa + (unsigned)(mb * 16) * RSB + ko + a_lane);
#pragma unroll
            for (int nb2 = 0; nb2 < 2; ++nb2) {
                LDSM4(bh[nb2][0], bh[nb2][1], bh[nb2][2], bh[nb2][3],
                      sb_ + (unsigned)(nb2 * 16) * RSB + ko + b_lane);
                LDSM4(bl[nb2][0], bl[nb2][1], bl[nb2][2], bl[nb2][3],
                      sb_ + BP + (unsigned)(nb2 * 16) * RSB + ko + b_lane);
            }
#pragma unroll
            for (int mb = 0; mb < 4; ++mb)
#pragma unroll
                for (int nb = 0; nb < 4; ++nb)
                    MMA16816(acc[mb][nb], ah[mb], &bh[nb >> 1][(nb & 1) * 2]);
#pragma unroll
            for (int mb = 0; mb < 4; ++mb)
#pragma unroll
                for (int nb = 0; nb < 4; ++nb)
                    MMA16816(acc[mb][nb], ah[mb], &bl[nb >> 1][(nb & 1) * 2]);
#pragma unroll
            for (int mb = 0; mb < 4; ++mb)
                LDSM4(ah[mb][0], ah[mb][1], ah[mb][2], ah[mb][3],
                      sa + AP + (unsigned)(mb * 16) * RSB + ko + a_lane);
#pragma unroll
            for (int mb = 0; mb < 4; ++mb)
#pragma unroll
                for (int nb = 0; nb < 4; ++nb)
                    MMA16816(acc[mb][nb], ah[mb], &bh[nb >> 1][(nb & 1) * 2]);
        }
        __syncthreads();                  // all warps done reading stage s

        if (c + 2 < NKCHUNK) cp_chunk(c + 2, s);
        CP_WAIT(1);                       // stage s^1 (chunk c+1) ready
        __syncthreads();
    }

    // ---- epilogue: bias + scattered store ----
    const int g   = lane >> 2;
    const int tig = lane & 3;
    const float* bg = bias + chunk * COUT + nt * BN + wn * 32;
    float* og = out + (size_t)(mt * BM + wm * 64) * IN_F + chunk * COUT + nt * BN + wn * 32;

#pragma unroll
    for (int mb = 0; mb < 4; ++mb) {
#pragma unroll
        for (int nb = 0; nb < 4; ++nb) {
            int col = nb * 8 + tig * 2;
            float b0 = bg[col], b1 = bg[col + 1];
            int r0 = mb * 16 + g;
            float2 v0 = make_float2(acc[mb][nb][0] + b0, acc[mb][nb][1] + b1);
            float2 v1 = make_float2(acc[mb][nb][2] + b0, acc[mb][nb][3] + b1);
            *(float2*)(og + (size_t)r0 * IN_F + col)       = v0;
            *(float2*)(og + (size_t)(r0 + 8) * IN_F + col) = v1;
        }
    }
}

// ---------------------------------------------------------------------------
extern "C" void kernel_launch(void* const* d_in, const int* in_sizes, int n_in,
                              void* d_out, int out_size) {
    const float* x    = (const float*)d_in[0];
    const float* W    = (const float*)d_in[1];
    const float* bias = (const float*)d_in[2];
    float* out        = (float*)d_out;
    float* out_act    = out + (size_t)BATCH * IN_F;

    cudaFuncSetAttribute(gemm_mma_kernel,
                         cudaFuncAttributeMaxDynamicSharedMemorySize, DSMEM_B);

    dim3 gact(NCHUNK, BATCH / 128);
    act_fused_kernel<<<gact, 256>>>(x, out_act);

    convert_kernel<<<XBLK + WBLK, 256>>>(x, W);

    dim3 ggemm(COUT / BN, BATCH / BM, TOPK);
    gemm_mma_kernel<<<ggemm, 256, DSMEM_B>>>(bias, out);
}

// round 15
// speedup vs baseline: 1.5310x; 1.5310x over previous
#include <cuda_runtime.h>
#include <cuda_bf16.h>

#define BATCH      8192
#define IN_F       4096
#define NCHUNK     8
#define CIN        512
#define COUT       512
#define TOPK       2

// GEMM tiling (mma.sync path)
#define BM         128
#define BN         128
#define KC         32                   // k elems per chunk-stage
#define NKCHUNK    (CIN / KC)           // 16
#define RS         40                   // padded bf16 row pitch (80 B)
#define RSB        (RS * 2)
#define AP         (BM * RSB)           // 10240 B per plane
#define BP         (BN * RSB)           // 10240 B
// smem layout: [Ahi][Alo][Bhi0][Blo0][Bhi1][Blo1][fp32A]
#define BS_OFF0    (2 * AP)             // 20480
#define BS_OFF1    (2 * AP + 2 * BP)    // 40960
#define FROW       128                  // fp32 A staging pitch (16B aligned)
#define FPA_OFF    (2 * AP + 4 * BP)    // 61440
#define DSMEM_B    (FPA_OFF + BM * FROW)   // 77824 -> occupancy 2

// Device-global scratch
__device__ float    g_act[NCHUNK];
__device__ unsigned g_tick;
__device__ int      g_idx[TOPK];
// W bf16 planes, ALL 8 chunks: [chunk][cout row][512 bf16] as uint2 (8B)
__device__ uint2 g_whi[NCHUNK * COUT * 128];
__device__ uint2 g_wlo[NCHUNK * COUT * 128];

__device__ __forceinline__ unsigned smem_u32(const void* p) {
    unsigned a;
    asm("{ .reg .u64 t; cvta.to.shared.u64 t, %1; cvt.u32.u64 %0, t; }"
        : "=r"(a) : "l"(p));
    return a;
}

#define LDSM4(r0, r1, r2, r3, addr)                                        \
    asm volatile("ldmatrix.sync.aligned.m8n8.x4.shared.b16 {%0,%1,%2,%3}, [%4];" \
        : "=r"(r0), "=r"(r1), "=r"(r2), "=r"(r3) : "r"(addr))

#define MMA16816(c, a, b)                                                  \
    asm volatile("mma.sync.aligned.m16n8k16.row.col.f32.bf16.bf16.f32 "    \
        "{%0,%1,%2,%3}, {%4,%5,%6,%7}, {%8,%9}, {%0,%1,%2,%3};"            \
        : "+f"((c)[0]), "+f"((c)[1]), "+f"((c)[2]), "+f"((c)[3])           \
        : "r"((a)[0]), "r"((a)[1]), "r"((a)[2]), "r"((a)[3]),              \
          "r"((b)[0]), "r"((b)[1]))

#define CP16(dst, src)                                                     \
    asm volatile("cp.async.cg.shared.global [%0], [%1], 16;"               \
        :: "r"(dst), "l"(src))
#define CP_COMMIT()  asm volatile("cp.async.commit_group;" ::: "memory")
#define CP_WAIT0()   asm volatile("cp.async.wait_group 0;" ::: "memory")

// ---------------------------------------------------------------------------
// split a float4 into packed bf16x2 hi (truncate) and lo (rn residual)
// ---------------------------------------------------------------------------
__device__ __forceinline__ void split4(float4 v, unsigned& hi01, unsigned& hi23,
                                       unsigned& lo01, unsigned& lo23) {
    unsigned u0 = __float_as_uint(v.x);
    unsigned u1 = __float_as_uint(v.y);
    unsigned u2 = __float_as_uint(v.z);
    unsigned u3 = __float_as_uint(v.w);
    hi01 = (u0 >> 16) | (u1 & 0xFFFF0000u);
    hi23 = (u2 >> 16) | (u3 & 0xFFFF0000u);
    float l0 = v.x - __uint_as_float(u0 & 0xFFFF0000u);
    float l1 = v.y - __uint_as_float(u1 & 0xFFFF0000u);
    float l2 = v.z - __uint_as_float(u2 & 0xFFFF0000u);
    float l3 = v.w - __uint_as_float(u3 & 0xFFFF0000u);
    __nv_bfloat162 p01 = __floats2bfloat162_rn(l0, l1);
    __nv_bfloat162 p23 = __floats2bfloat162_rn(l2, l3);
    lo01 = *(unsigned*)&p01;
    lo23 = *(unsigned*)&p23;
}

// ---------------------------------------------------------------------------
// 1) act + finalize (ticket) + W->bf16 planes (all 8 chunks, no g_idx dep).
//    grid = (9, 64): x<8 -> activity blocks; x==8 -> W convert blocks.
// ---------------------------------------------------------------------------
__global__ __launch_bounds__(256) void act_fused_kernel(
    const float* __restrict__ x, const float* __restrict__ W,
    float* __restrict__ out_act)
{
    if (blockIdx.x == NCHUNK) {
        // W convert: 524288 float4 total, 64 blocks -> 32 per thread (linear)
        const int base = blockIdx.y * 256 + threadIdx.x;    // 0..16383
#pragma unroll 4
        for (int it = 0; it < 32; ++it) {
            const int e = base + it * 16384;                // 0..524287
            float4 v = ((const float4*)W)[e];
            unsigned h01, h23, l01, l23;
            split4(v, h01, h23, l01, l23);
            g_whi[e] = make_uint2(h01, h23);
            g_wlo[e] = make_uint2(l01, l23);
        }
        return;
    }

    const int c       = blockIdx.x;
    const int rowbase = blockIdx.y * 128;
    const float* base = x + (size_t)rowbase * IN_F + c * CIN;

    float s = 0.0f;
#pragma unroll 4
    for (int it = 0; it < 64; ++it) {
        int lin = it * 256 + threadIdx.x;
        int r   = lin >> 7;
        int c4  = (lin & 127) << 2;
        float4 v = *(const float4*)(base + (size_t)r * IN_F + c4);
        s += fabsf(v.x) + fabsf(v.y) + fabsf(v.z) + fabsf(v.w);
    }
#pragma unroll
    for (int off = 16; off; off >>= 1) s += __shfl_xor_sync(0xffffffffu, s, off);
    __shared__ float ws[8];
    if ((threadIdx.x & 31) == 0) ws[threadIdx.x >> 5] = s;
    __syncthreads();
    if (threadIdx.x == 0) {
        s = ws[0];
#pragma unroll
        for (int i = 1; i < 8; ++i) s += ws[i];
        atomicAdd(&g_act[c], s);
        __threadfence();
        unsigned t = atomicAdd(&g_tick, 1u);
        if (t == (unsigned)(NCHUNK * 64 - 1)) {
            const float inv = 1.0f / ((float)BATCH * (float)CIN);
            float a[NCHUNK];
#pragma unroll
            for (int i = 0; i < NCHUNK; ++i) {
                a[i] = g_act[i] * inv;
                out_act[i] = a[i];
            }
            int i0 = 0;
#pragma unroll
            for (int i = 1; i < NCHUNK; ++i) if (a[i] > a[i0]) i0 = i;
            int i1 = (i0 == 0) ? 1 : 0;
#pragma unroll
            for (int i = 0; i < NCHUNK; ++i) if (i != i0 && a[i] > a[i1]) i1 = i;
            g_idx[0] = i0;
            g_idx[1] = i1;
#pragma unroll
            for (int i = 0; i < NCHUNK; ++i) g_act[i] = 0.0f;
            g_tick = 0u;
            __threadfence();
        }
    }
}

// ---------------------------------------------------------------------------
// 2) GEMM (3xBF16 split, mma.sync): A = R7 path (fp32 cp.async + in-kernel
//    split), B = direct cp.async of pre-converted bf16 planes (double-buffered).
//    Folded zeroing of non-selected chunks. grid=(4,64,2), 256 thr, occ 2.
// ---------------------------------------------------------------------------
__global__ __launch_bounds__(256, 2) void gemm_mma_kernel(
    const float* __restrict__ x, const float* __restrict__ bias,
    float* __restrict__ out)
{
    extern __shared__ char dsm[];
    const unsigned smb = smem_u32(dsm);

    const int tid  = threadIdx.x;
    const int lane = tid & 31;
    const int wid  = tid >> 5;
    const int wm   = wid & 1;             // 2 m-warps (64 rows)
    const int wn   = wid >> 1;            // 4 n-warps (32 cols)

    const int nt    = blockIdx.x;         // 0..3
    const int mt    = blockIdx.y;         // 0..63
    const int zz    = blockIdx.z;         // 0..1
    const int chunk = g_idx[zz];
    const int zslot = nt + 4 * zz;        // 0..7 -> 64-col zero slice

    int nz[6];
    {
        int s0 = g_idx[0], s1 = g_idx[1], k = 0;
#pragma unroll
        for (int i = 0; i < NCHUNK; ++i)
            if (i != s0 && i != s1) nz[k++] = i;
    }

    const float* xg = x + (size_t)(mt * BM) * IN_F + chunk * CIN;
    const char*  wh = (const char*)g_whi
        + ((size_t)chunk * COUT + (size_t)nt * BN) * 1024;
    const char*  wl = (const char*)g_wlo
        + ((size_t)chunk * COUT + (size_t)nt * BN) * 1024;

    // A cp/produce mapping (per-thread self-consistent): row=(tid>>3)+32it, q=tid&7
    const int grow = tid >> 3;
    const int gf4  = tid & 7;
    // B cp mapping: row=(tid>>2)+64it, q=tid&3
    const int crow = tid >> 2;
    const int cq   = tid & 3;

    const unsigned a_lane = (unsigned)(((lane & 7) + ((lane >> 3) & 1) * 8) * RSB
                                       + ((lane >> 4) & 1) * 16);
    const unsigned b_lane = (unsigned)((((lane >> 4) & 1) * 8 + (lane & 7)) * RSB
                                       + ((lane >> 3) & 1) * 16);

    const unsigned fA = smb + FPA_OFF;

    float acc[4][4][4];
#pragma unroll
    for (int i = 0; i < 4; ++i)
#pragma unroll
        for (int j = 0; j < 4; ++j)
#pragma unroll
            for (int k = 0; k < 4; ++k) acc[i][j][k] = 0.0f;

    // cp chunk c: A fp32 -> fA buf, B bf16 planes -> B stage s
    auto cp_chunk = [&](int c, int s) {
        const int k0 = c * KC;            // fp32 elem offset
        const int kb = c * 64;            // bf16 byte offset (32 elems)
#pragma unroll
        for (int it = 0; it < 4; ++it) {
            int row = grow + it * 32;
            CP16(fA + row * FROW + gf4 * 16,
                 xg + (size_t)row * IN_F + k0 + gf4 * 4);
        }
        const unsigned bs = smb + (s ? BS_OFF1 : BS_OFF0);
#pragma unroll
        for (int it = 0; it < 2; ++it) {
            int row = crow + it * 64;
            unsigned d = bs + row * RSB + cq * 16;
            CP16(d,      wh + (size_t)row * 1024 + kb + cq * 16);
            CP16(d + BP, wl + (size_t)row * 1024 + kb + cq * 16);
        }
        CP_COMMIT();
    };

    // produce A: fp32 stage -> split -> Ahi/Alo (reads own-thread cp'd coords)
    auto produceA = [&]() {
#pragma unroll
        for (int it = 0; it < 4; ++it) {
            int row = grow + it * 32;
            float4 va = *(const float4*)(dsm + FPA_OFF + row * FROW + gf4 * 16);
            unsigned h01, h23, l01, l23;
            split4(va, h01, h23, l01, l23);
            *(uint2*)(dsm + row * RSB + gf4 * 8)      = make_uint2(h01, h23);
            *(uint2*)(dsm + AP + row * RSB + gf4 * 8) = make_uint2(l01, l23);
        }
    };

    // prologue: chunk 0
    cp_chunk(0, 0);
    CP_WAIT0();
    produceA();
    __syncthreads();

    for (int c = 0; c < NKCHUNK; ++c) {
        const int s = c & 1;
        if (c + 1 < NKCHUNK) cp_chunk(c + 1, s ^ 1);

        // folded zeroing (independent STG.128, overlaps MMA)
#pragma unroll
        for (int j = 0; j < 3; ++j) {
            int e   = (c * 3 + j) * 256 + tid;
            int f4c = e & 15;
            int row = (e >> 4) & 127;
            int c6  = e >> 11;
            float4* dst = (float4*)out
                + (size_t)(mt * 128 + row) * (IN_F / 4)
                + nz[c6] * (COUT / 4) + zslot * 16 + f4c;
            *dst = make_float4(0.f, 0.f, 0.f, 0.f);
        }

        // ---- MMA: A bf16 stage (chunk c) x B stage s (chunk c) ----
        const unsigned sa  = smb + (unsigned)(wm * 64) * RSB;
        const unsigned sb_ = smb + (s ? BS_OFF1 : BS_OFF0)
                           + (unsigned)(wn * 32) * RSB;
#pragma unroll
        for (int ks = 0; ks < 2; ++ks) {
            const unsigned ko = (unsigned)ks * 32;
            unsigned ah[4][4], bh[2][4], bl[2][4];
#pragma unroll
            for (int mb = 0; mb < 4; ++mb)
                LDSM4(ah[mb][0], ah[mb][1], ah[mb][2], ah[mb][3],
                      sa + (unsigned)(mb * 16) * RSB + ko + a_lane);
#pragma unroll
            for (int nb2 = 0; nb2 < 2; ++nb2) {
                LDSM4(bh[nb2][0], bh[nb2][1], bh[nb2][2], bh[nb2][3],
                      sb_ + (unsigned)(nb2 * 16) * RSB + ko + b_lane);
                LDSM4(bl[nb2][0], bl[nb2][1], bl[nb2][2], bl[nb2][3],
                      sb_ + BP + (unsigned)(nb2 * 16) * RSB + ko + b_lane);
            }
#pragma unroll
            for (int mb = 0; mb < 4; ++mb)
#pragma unroll
                for (int nb = 0; nb < 4; ++nb)
                    MMA16816(acc[mb][nb], ah[mb], &bh[nb >> 1][(nb & 1) * 2]);
#pragma unroll
            for (int mb = 0; mb < 4; ++mb)
#pragma unroll
                for (int nb = 0; nb < 4; ++nb)
                    MMA16816(acc[mb][nb], ah[mb], &bl[nb >> 1][(nb & 1) * 2]);
#pragma unroll
            for (int mb = 0; mb < 4; ++mb)
                LDSM4(ah[mb][0], ah[mb][1], ah[mb][2], ah[mb][3],
                      sa + AP + (unsigned)(mb * 16) * RSB + ko + a_lane);
#pragma unroll
            for (int mb = 0; mb < 4; ++mb)
#pragma unroll
                for (int nb = 0; nb < 4; ++nb)
                    MMA16816(acc[mb][nb], ah[mb], &bh[nb >> 1][(nb & 1) * 2]);
        }
        __syncthreads();                  // all warps done with A stage + B(s)

        if (c + 1 < NKCHUNK) {
            CP_WAIT0();                   // chunk c+1 (A fp32 + B bf16) landed
            produceA();                   // A bf16 stage := chunk c+1
        }
        __syncthreads();
    }

    // ---- epilogue: bias + scattered store ----
    const int g   = lane >> 2;
    const int tig = lane & 3;
    const float* bg = bias + chunk * COUT + nt * BN + wn * 32;
    float* og = out + (size_t)(mt * BM + wm * 64) * IN_F + chunk * COUT + nt * BN + wn * 32;

#pragma unroll
    for (int mb = 0; mb < 4; ++mb) {
#pragma unroll
        for (int nb = 0; nb < 4; ++nb) {
            int col = nb * 8 + tig * 2;
            float b0 = bg[col], b1 = bg[col + 1];
            int r0 = mb * 16 + g;
            float2 v0 = make_float2(acc[mb][nb][0] + b0, acc[mb][nb][1] + b1);
            float2 v1 = make_float2(acc[mb][nb][2] + b0, acc[mb][nb][3] + b1);
            *(float2*)(og + (size_t)r0 * IN_F + col)       = v0;
            *(float2*)(og + (size_t)(r0 + 8) * IN_F + col) = v1;
        }
    }
}

// ---------------------------------------------------------------------------
extern "C" void kernel_launch(void* const* d_in, const int* in_sizes, int n_in,
                              void* d_out, int out_size) {
    const float* x    = (const float*)d_in[0];
    const float* W    = (const float*)d_in[1];
    const float* bias = (const float*)d_in[2];
    float* out        = (float*)d_out;
    float* out_act    = out + (size_t)BATCH * IN_F;

    cudaFuncSetAttribute(gemm_mma_kernel,
                         cudaFuncAttributeMaxDynamicSharedMemorySize, DSMEM_B);

    dim3 gact(NCHUNK + 1, BATCH / 128);
    act_fused_kernel<<<gact, 256>>>(x, W, out_act);

    dim3 ggemm(COUT / BN, BATCH / BM, TOPK);
    gemm_mma_kernel<<<ggemm, 256, DSMEM_B>>>(x, bias, out);
}

// round 16
// speedup vs baseline: 1.9122x; 1.2490x over previous
#include <cuda_runtime.h>
#include <cuda_fp16.h>

#define BATCH      8192
#define IN_F       4096
#define NCHUNK     8
#define CIN        512
#define COUT       512
#define TOPK       2

// GEMM tiling (mma.sync fp16 path)
#define BM         128
#define BN         128
#define KC         32                   // k elems per chunk-stage
#define NKCHUNK    (CIN / KC)           // 16
#define RS         40                   // padded fp16 row pitch (80 B)
#define RSB        (RS * 2)
#define AP         (BM * RSB)           // 10240 B per plane
#define BP         (BN * RSB)           // 10240 B
// smem layout: [Ahi][Alo][B stage0][B stage1][fp32A]
#define BS_OFF0    (2 * AP)             // 20480
#define BS_OFF1    (2 * AP + BP)        // 30720
#define FROW       128                  // fp32 A staging pitch (16B aligned)
#define FPA_OFF    (2 * AP + 2 * BP)    // 40960
#define DSMEM_B    (FPA_OFF + BM * FROW)   // 57344 -> occupancy 2

#define ACT_YBLK   128                  // 64 rows per activity block

// Device-global scratch
__device__ float    g_act[NCHUNK];
__device__ unsigned g_tick;
__device__ int      g_idx[TOPK];
// W fp16 plane, ALL 8 chunks: [chunk][cout row][512 fp16] as uint2 (8B = 4 fp16)
__device__ uint2 g_wh[NCHUNK * COUT * 128];

__device__ __forceinline__ unsigned smem_u32(const void* p) {
    unsigned a;
    asm("{ .reg .u64 t; cvta.to.shared.u64 t, %1; cvt.u32.u64 %0, t; }"
        : "=r"(a) : "l"(p));
    return a;
}

#define LDSM4(r0, r1, r2, r3, addr)                                        \
    asm volatile("ldmatrix.sync.aligned.m8n8.x4.shared.b16 {%0,%1,%2,%3}, [%4];" \
        : "=r"(r0), "=r"(r1), "=r"(r2), "=r"(r3) : "r"(addr))

#define MMA16816(c, a, b)                                                  \
    asm volatile("mma.sync.aligned.m16n8k16.row.col.f32.f16.f16.f32 "      \
        "{%0,%1,%2,%3}, {%4,%5,%6,%7}, {%8,%9}, {%0,%1,%2,%3};"            \
        : "+f"((c)[0]), "+f"((c)[1]), "+f"((c)[2]), "+f"((c)[3])           \
        : "r"((a)[0]), "r"((a)[1]), "r"((a)[2]), "r"((a)[3]),              \
          "r"((b)[0]), "r"((b)[1]))

#define CP16(dst, src)                                                     \
    asm volatile("cp.async.cg.shared.global [%0], [%1], 16;"               \
        :: "r"(dst), "l"(src))
#define CP_COMMIT()  asm volatile("cp.async.commit_group;" ::: "memory")
#define CP_WAIT0()   asm volatile("cp.async.wait_group 0;" ::: "memory")

// ---------------------------------------------------------------------------
// fp16 helpers: W quantize (rn) and A hi/lo split
// ---------------------------------------------------------------------------
__device__ __forceinline__ uint2 pack4h(float4 v) {
    __half2 h01 = __floats2half2_rn(v.x, v.y);
    __half2 h23 = __floats2half2_rn(v.z, v.w);
    return make_uint2(*(unsigned*)&h01, *(unsigned*)&h23);
}

__device__ __forceinline__ void split4h(float4 v, uint2& hi, uint2& lo) {
    __half2 h01 = __floats2half2_rn(v.x, v.y);
    __half2 h23 = __floats2half2_rn(v.z, v.w);
    float2 f01 = __half22float2(h01);
    float2 f23 = __half22float2(h23);
    __half2 l01 = __floats2half2_rn(v.x - f01.x, v.y - f01.y);
    __half2 l23 = __floats2half2_rn(v.z - f23.x, v.w - f23.y);
    hi = make_uint2(*(unsigned*)&h01, *(unsigned*)&h23);
    lo = make_uint2(*(unsigned*)&l01, *(unsigned*)&l23);
}

// ---------------------------------------------------------------------------
// 1) act + finalize (ticket) + W->fp16 plane (all 8 chunks).
//    grid = (9, ACT_YBLK): x<8 -> activity (64 rows each); x==8 -> W convert.
// ---------------------------------------------------------------------------
__global__ __launch_bounds__(256) void act_fused_kernel(
    const float* __restrict__ x, const float* __restrict__ W,
    float* __restrict__ out_act)
{
    if (blockIdx.x == NCHUNK) {
        // W convert: 524288 float4 over ACT_YBLK blocks -> 16 per thread
        const int base = blockIdx.y * 256 + threadIdx.x;    // 0..32767
#pragma unroll 4
        for (int it = 0; it < 16; ++it) {
            const int e = base + it * (ACT_YBLK * 256);     // 0..524287
            g_wh[e] = pack4h(((const float4*)W)[e]);
        }
        return;
    }

    const int c       = blockIdx.x;
    const int rowbase = blockIdx.y * 64;
    const float* base = x + (size_t)rowbase * IN_F + c * CIN;

    float s = 0.0f;
#pragma unroll 4
    for (int it = 0; it < 32; ++it) {
        int lin = it * 256 + threadIdx.x;      // 0..8191
        int r   = lin >> 7;
        int c4  = (lin & 127) << 2;
        float4 v = *(const float4*)(base + (size_t)r * IN_F + c4);
        s += fabsf(v.x) + fabsf(v.y) + fabsf(v.z) + fabsf(v.w);
    }
#pragma unroll
    for (int off = 16; off; off >>= 1) s += __shfl_xor_sync(0xffffffffu, s, off);
    __shared__ float ws[8];
    if ((threadIdx.x & 31) == 0) ws[threadIdx.x >> 5] = s;
    __syncthreads();
    if (threadIdx.x == 0) {
        s = ws[0];
#pragma unroll
        for (int i = 1; i < 8; ++i) s += ws[i];
        atomicAdd(&g_act[c], s);
        __threadfence();
        unsigned t = atomicAdd(&g_tick, 1u);
        if (t == (unsigned)(NCHUNK * ACT_YBLK - 1)) {
            const float inv = 1.0f / ((float)BATCH * (float)CIN);
            float a[NCHUNK];
#pragma unroll
            for (int i = 0; i < NCHUNK; ++i) {
                a[i] = g_act[i] * inv;
                out_act[i] = a[i];
            }
            int i0 = 0;
#pragma unroll
            for (int i = 1; i < NCHUNK; ++i) if (a[i] > a[i0]) i0 = i;
            int i1 = (i0 == 0) ? 1 : 0;
#pragma unroll
            for (int i = 0; i < NCHUNK; ++i) if (i != i0 && a[i] > a[i1]) i1 = i;
            g_idx[0] = i0;
            g_idx[1] = i1;
#pragma unroll
            for (int i = 0; i < NCHUNK; ++i) g_act[i] = 0.0f;
            g_tick = 0u;
            __threadfence();
        }
    }
}

// ---------------------------------------------------------------------------
// 2) GEMM (2xFP16 split: Ahi*B + Alo*B), mma.sync, folded zeroing.
//    A: fp32 cp.async + in-kernel fp16 split. B: direct cp.async of fp16 plane.
//    grid = (4, 64, 2), 256 threads, occupancy 2.
// ---------------------------------------------------------------------------
__global__ __launch_bounds__(256, 2) void gemm_mma_kernel(
    const float* __restrict__ x, const float* __restrict__ bias,
    float* __restrict__ out)
{
    extern __shared__ char dsm[];
    const unsigned smb = smem_u32(dsm);

    const int tid  = threadIdx.x;
    const int lane = tid & 31;
    const int wid  = tid >> 5;
    const int wm   = wid & 1;             // 2 m-warps (64 rows)
    const int wn   = wid >> 1;            // 4 n-warps (32 cols)

    const int nt    = blockIdx.x;         // 0..3
    const int mt    = blockIdx.y;         // 0..63
    const int zz    = blockIdx.z;         // 0..1
    const int chunk = g_idx[zz];
    const int zslot = nt + 4 * zz;        // 0..7 -> 64-col zero slice

    int nz[6];
    {
        int s0 = g_idx[0], s1 = g_idx[1], k = 0;
#pragma unroll
        for (int i = 0; i < NCHUNK; ++i)
            if (i != s0 && i != s1) nz[k++] = i;
    }

    const float* xg = x + (size_t)(mt * BM) * IN_F + chunk * CIN;
    const char*  wh = (const char*)g_wh
        + ((size_t)chunk * COUT + (size_t)nt * BN) * 1024;

    // A cp/produce mapping: row=(tid>>3)+32it, q=tid&7
    const int grow = tid >> 3;
    const int gf4  = tid & 7;
    // B cp mapping: row=(tid>>2)+64it, q=tid&3
    const int crow = tid >> 2;
    const int cq   = tid & 3;

    const unsigned a_lane = (unsigned)(((lane & 7) + ((lane >> 3) & 1) * 8) * RSB
                                       + ((lane >> 4) & 1) * 16);
    const unsigned b_lane = (unsigned)((((lane >> 4) & 1) * 8 + (lane & 7)) * RSB
                                       + ((lane >> 3) & 1) * 16);

    const unsigned fA = smb + FPA_OFF;

    float acc[4][4][4];
#pragma unroll
    for (int i = 0; i < 4; ++i)
#pragma unroll
        for (int j = 0; j < 4; ++j)
#pragma unroll
            for (int k = 0; k < 4; ++k) acc[i][j][k] = 0.0f;

    // cp chunk c: A fp32 -> fA buf, B fp16 plane -> B stage s
    auto cp_chunk = [&](int c, int s) {
        const int k0 = c * KC;            // fp32 elem offset
        const int kb = c * 64;            // fp16 byte offset (32 elems)
#pragma unroll
        for (int it = 0; it < 4; ++it) {
            int row = grow + it * 32;
            CP16(fA + row * FROW + gf4 * 16,
                 xg + (size_t)row * IN_F + k0 + gf4 * 4);
        }
        const unsigned bs = smb + (s ? BS_OFF1 : BS_OFF0);
#pragma unroll
        for (int it = 0; it < 2; ++it) {
            int row = crow + it * 64;
            CP16(bs + row * RSB + cq * 16,
                 wh + (size_t)row * 1024 + kb + cq * 16);
        }
        CP_COMMIT();
    };

    // produce A: fp32 stage -> fp16 split -> Ahi/Alo
    auto produceA = [&]() {
#pragma unroll
        for (int it = 0; it < 4; ++it) {
            int row = grow + it * 32;
            float4 va = *(const float4*)(dsm + FPA_OFF + row * FROW + gf4 * 16);
            uint2 hi, lo;
            split4h(va, hi, lo);
            *(uint2*)(dsm + row * RSB + gf4 * 8)      = hi;
            *(uint2*)(dsm + AP + row * RSB + gf4 * 8) = lo;
        }
    };

    // prologue: chunk 0
    cp_chunk(0, 0);
    CP_WAIT0();
    produceA();
    __syncthreads();

    for (int c = 0; c < NKCHUNK; ++c) {
        const int s = c & 1;
        if (c + 1 < NKCHUNK) cp_chunk(c + 1, s ^ 1);

        // folded zeroing (independent STG.128, overlaps MMA)
#pragma unroll
        for (int j = 0; j < 3; ++j) {
            int e   = (c * 3 + j) * 256 + tid;
            int f4c = e & 15;
            int row = (e >> 4) & 127;
            int c6  = e >> 11;
            float4* dst = (float4*)out
                + (size_t)(mt * 128 + row) * (IN_F / 4)
                + nz[c6] * (COUT / 4) + zslot * 16 + f4c;
            *dst = make_float4(0.f, 0.f, 0.f, 0.f);
        }

        // ---- MMA: (Ahi + Alo) x B(stage s), chunk c ----
        const unsigned sa  = smb + (unsigned)(wm * 64) * RSB;
        const unsigned sb_ = smb + (s ? BS_OFF1 : BS_OFF0)
                           + (unsigned)(wn * 32) * RSB;
#pragma unroll
        for (int ks = 0; ks < 2; ++ks) {
            const unsigned ko = (unsigned)ks * 32;
            unsigned ah[4][4], bh[2][4];
#pragma unroll
            for (int mb = 0; mb < 4; ++mb)
                LDSM4(ah[mb][0], ah[mb][1], ah[mb][2], ah[mb][3],
                      sa + (unsigned)(mb * 16) * RSB + ko + a_lane);
#pragma unroll
            for (int nb2 = 0; nb2 < 2; ++nb2)
                LDSM4(bh[nb2][0], bh[nb2][1], bh[nb2][2], bh[nb2][3],
                      sb_ + (unsigned)(nb2 * 16) * RSB + ko + b_lane);
            // pass 1: Ahi * B
#pragma unroll
            for (int mb = 0; mb < 4; ++mb)
#pragma unroll
                for (int nb = 0; nb < 4; ++nb)
                    MMA16816(acc[mb][nb], ah[mb], &bh[nb >> 1][(nb & 1) * 2]);
            // load Alo over ah, pass 2: Alo * B
#pragma unroll
            for (int mb = 0; mb < 4; ++mb)
                LDSM4(ah[mb][0], ah[mb][1], ah[mb][2], ah[mb][3],
                      sa + AP + (unsigned)(mb * 16) * RSB + ko + a_lane);
#pragma unroll
            for (int mb = 0; mb < 4; ++mb)
#pragma unroll
                for (int nb = 0; nb < 4; ++nb)
                    MMA16816(acc[mb][nb], ah[mb], &bh[nb >> 1][(nb & 1) * 2]);
        }
        __syncthreads();                  // all warps done with A stage + B(s)

        if (c + 1 < NKCHUNK) {
            CP_WAIT0();                   // chunk c+1 (A fp32 + B fp16) landed
            produceA();                   // A stages := chunk c+1
        }
        __syncthreads();
    }

    // ---- epilogue: bias + scattered store ----
    const int g   = lane >> 2;
    const int tig = lane & 3;
    const float* bg = bias + chunk * COUT + nt * BN + wn * 32;
    float* og = out + (size_t)(mt * BM + wm * 64) * IN_F + chunk * COUT + nt * BN + wn * 32;

#pragma unroll
    for (int mb = 0; mb < 4; ++mb) {
#pragma unroll
        for (int nb = 0; nb < 4; ++nb) {
            int col = nb * 8 + tig * 2;
            float b0 = bg[col], b1 = bg[col + 1];
            int r0 = mb * 16 + g;
            float2 v0 = make_float2(acc[mb][nb][0] + b0, acc[mb][nb][1] + b1);
            float2 v1 = make_float2(acc[mb][nb][2] + b0, acc[mb][nb][3] + b1);
            *(float2*)(og + (size_t)r0 * IN_F + col)       = v0;
            *(float2*)(og + (size_t)(r0 + 8) * IN_F + col) = v1;
        }
    }
}

// ---------------------------------------------------------------------------
extern "C" void kernel_launch(void* const* d_in, const int* in_sizes, int n_in,
                              void* d_out, int out_size) {
    const float* x    = (const float*)d_in[0];
    const float* W    = (const float*)d_in[1];
    const float* bias = (const float*)d_in[2];
    float* out        = (float*)d_out;
    float* out_act    = out + (size_t)BATCH * IN_F;

    cudaFuncSetAttribute(gemm_mma_kernel,
                         cudaFuncAttributeMaxDynamicSharedMemorySize, DSMEM_B);

    dim3 gact(NCHUNK + 1, ACT_YBLK);
    act_fused_kernel<<<gact, 256>>>(x, W, out_act);

    dim3 ggemm(COUT / BN, BATCH / BM, TOPK);
    gemm_mma_kernel<<<ggemm, 256, DSMEM_B>>>(x, bias, out);
}

// round 17
// speedup vs baseline: 2.2367x; 1.1697x over previous
#include <cuda_runtime.h>
#include <cuda_fp16.h>

#define BATCH      8192
#define IN_F       4096
#define NCHUNK     8
#define CIN        512
#define COUT       512
#define TOPK       2

// GEMM tiling (mma.sync fp16, single pass)
#define BM         128
#define BN         128
#define KC         32                   // k elems per chunk-stage
#define NKCHUNK    (CIN / KC)           // 16
#define RS         40                   // padded fp16 row pitch (80 B)
#define RSB        (RS * 2)
#define AP         (BM * RSB)           // 10240 B (single A plane)
#define BP         (BN * RSB)           // 10240 B
// smem layout: [A][B stage0][B stage1][fp32A]
#define BS_OFF0    (AP)                 // 10240
#define BS_OFF1    (AP + BP)            // 20480
#define FROW       128                  // fp32 A staging pitch (16B aligned)
#define FPA_OFF    (AP + 2 * BP)        // 30720
#define DSMEM_B    (FPA_OFF + BM * FROW)   // 47104 -> occupancy 2

#define ACT_YBLK   128                  // 64 rows per activity block

// Device-global scratch
__device__ float    g_act[NCHUNK];
__device__ unsigned g_tick;
__device__ int      g_idx[TOPK];
// W fp16 plane, ALL 8 chunks: [chunk][cout row][512 fp16] as uint2 (8B = 4 fp16)
__device__ uint2 g_wh[NCHUNK * COUT * 128];

__device__ __forceinline__ unsigned smem_u32(const void* p) {
    unsigned a;
    asm("{ .reg .u64 t; cvta.to.shared.u64 t, %1; cvt.u32.u64 %0, t; }"
        : "=r"(a) : "l"(p));
    return a;
}

#define LDSM4(r0, r1, r2, r3, addr)                                        \
    asm volatile("ldmatrix.sync.aligned.m8n8.x4.shared.b16 {%0,%1,%2,%3}, [%4];" \
        : "=r"(r0), "=r"(r1), "=r"(r2), "=r"(r3) : "r"(addr))

#define MMA16816(c, a, b)                                                  \
    asm volatile("mma.sync.aligned.m16n8k16.row.col.f32.f16.f16.f32 "      \
        "{%0,%1,%2,%3}, {%4,%5,%6,%7}, {%8,%9}, {%0,%1,%2,%3};"            \
        : "+f"((c)[0]), "+f"((c)[1]), "+f"((c)[2]), "+f"((c)[3])           \
        : "r"((a)[0]), "r"((a)[1]), "r"((a)[2]), "r"((a)[3]),              \
          "r"((b)[0]), "r"((b)[1]))

#define CP16(dst, src)                                                     \
    asm volatile("cp.async.cg.shared.global [%0], [%1], 16;"               \
        :: "r"(dst), "l"(src))
#define CP_COMMIT()  asm volatile("cp.async.commit_group;" ::: "memory")
#define CP_WAIT0()   asm volatile("cp.async.wait_group 0;" ::: "memory")

// ---------------------------------------------------------------------------
// fp16 pack helpers
// ---------------------------------------------------------------------------
__device__ __forceinline__ uint2 pack4h(float4 v) {
    __half2 h01 = __floats2half2_rn(v.x, v.y);
    __half2 h23 = __floats2half2_rn(v.z, v.w);
    return make_uint2(*(unsigned*)&h01, *(unsigned*)&h23);
}

// ---------------------------------------------------------------------------
// 1) act + finalize (ticket) + W->fp16 plane (all 8 chunks).
//    grid = (9, ACT_YBLK): x<8 -> activity (64 rows each); x==8 -> W convert.
// ---------------------------------------------------------------------------
__global__ __launch_bounds__(256) void act_fused_kernel(
    const float* __restrict__ x, const float* __restrict__ W,
    float* __restrict__ out_act)
{
    if (blockIdx.x == NCHUNK) {
        const int base = blockIdx.y * 256 + threadIdx.x;    // 0..32767
#pragma unroll 4
        for (int it = 0; it < 16; ++it) {
            const int e = base + it * (ACT_YBLK * 256);     // 0..524287
            g_wh[e] = pack4h(((const float4*)W)[e]);
        }
        return;
    }

    const int c       = blockIdx.x;
    const int rowbase = blockIdx.y * 64;
    const float* base = x + (size_t)rowbase * IN_F + c * CIN;

    float s = 0.0f;
#pragma unroll 4
    for (int it = 0; it < 32; ++it) {
        int lin = it * 256 + threadIdx.x;      // 0..8191
        int r   = lin >> 7;
        int c4  = (lin & 127) << 2;
        float4 v = *(const float4*)(base + (size_t)r * IN_F + c4);
        s += fabsf(v.x) + fabsf(v.y) + fabsf(v.z) + fabsf(v.w);
    }
#pragma unroll
    for (int off = 16; off; off >>= 1) s += __shfl_xor_sync(0xffffffffu, s, off);
    __shared__ float ws[8];
    if ((threadIdx.x & 31) == 0) ws[threadIdx.x >> 5] = s;
    __syncthreads();
    if (threadIdx.x == 0) {
        s = ws[0];
#pragma unroll
        for (int i = 1; i < 8; ++i) s += ws[i];
        atomicAdd(&g_act[c], s);
        __threadfence();
        unsigned t = atomicAdd(&g_tick, 1u);
        if (t == (unsigned)(NCHUNK * ACT_YBLK - 1)) {
            const float inv = 1.0f / ((float)BATCH * (float)CIN);
            float a[NCHUNK];
#pragma unroll
            for (int i = 0; i < NCHUNK; ++i) {
                a[i] = g_act[i] * inv;
                out_act[i] = a[i];
            }
            int i0 = 0;
#pragma unroll
            for (int i = 1; i < NCHUNK; ++i) if (a[i] > a[i0]) i0 = i;
            int i1 = (i0 == 0) ? 1 : 0;
#pragma unroll
            for (int i = 0; i < NCHUNK; ++i) if (i != i0 && a[i] > a[i1]) i1 = i;
            g_idx[0] = i0;
            g_idx[1] = i1;
#pragma unroll
            for (int i = 0; i < NCHUNK; ++i) g_act[i] = 0.0f;
            g_tick = 0u;
            __threadfence();
        }
    }
}

// ---------------------------------------------------------------------------
// 2) GEMM (single-pass fp16, mma.sync) + folded zeroing.
//    A: fp32 cp.async + in-kernel fp16 round. B: direct cp.async of fp16 plane.
//    grid = (4, 64, 2), 256 threads, occupancy 2.
// ---------------------------------------------------------------------------
__global__ __launch_bounds__(256, 2) void gemm_mma_kernel(
    const float* __restrict__ x, const float* __restrict__ bias,
    float* __restrict__ out)
{
    extern __shared__ char dsm[];
    const unsigned smb = smem_u32(dsm);

    const int tid  = threadIdx.x;
    const int lane = tid & 31;
    const int wid  = tid >> 5;
    const int wm   = wid & 1;             // 2 m-warps (64 rows)
    const int wn   = wid >> 1;            // 4 n-warps (32 cols)

    const int nt    = blockIdx.x;         // 0..3
    const int mt    = blockIdx.y;         // 0..63
    const int zz    = blockIdx.z;         // 0..1
    const int chunk = g_idx[zz];
    const int zslot = nt + 4 * zz;        // 0..7 -> 64-col zero slice

    int nz[6];
    {
        int s0 = g_idx[0], s1 = g_idx[1], k = 0;
#pragma unroll
        for (int i = 0; i < NCHUNK; ++i)
            if (i != s0 && i != s1) nz[k++] = i;
    }

    const float* xg = x + (size_t)(mt * BM) * IN_F + chunk * CIN;
    const char*  wh = (const char*)g_wh
        + ((size_t)chunk * COUT + (size_t)nt * BN) * 1024;

    // A cp/produce mapping: row=(tid>>3)+32it, q=tid&7
    const int grow = tid >> 3;
    const int gf4  = tid & 7;
    // B cp mapping: row=(tid>>2)+64it, q=tid&3
    const int crow = tid >> 2;
    const int cq   = tid & 3;

    const unsigned a_lane = (unsigned)(((lane & 7) + ((lane >> 3) & 1) * 8) * RSB
                                       + ((lane >> 4) & 1) * 16);
    const unsigned b_lane = (unsigned)((((lane >> 4) & 1) * 8 + (lane & 7)) * RSB
                                       + ((lane >> 3) & 1) * 16);

    const unsigned fA = smb + FPA_OFF;

    float acc[4][4][4];
#pragma unroll
    for (int i = 0; i < 4; ++i)
#pragma unroll
        for (int j = 0; j < 4; ++j)
#pragma unroll
            for (int k = 0; k < 4; ++k) acc[i][j][k] = 0.0f;

    // cp chunk c: A fp32 -> fA buf, B fp16 plane -> B stage s
    auto cp_chunk = [&](int c, int s) {
        const int k0 = c * KC;            // fp32 elem offset
        const int kb = c * 64;            // fp16 byte offset (32 elems)
#pragma unroll
        for (int it = 0; it < 4; ++it) {
            int row = grow + it * 32;
            CP16(fA + row * FROW + gf4 * 16,
                 xg + (size_t)row * IN_F + k0 + gf4 * 4);
        }
        const unsigned bs = smb + (s ? BS_OFF1 : BS_OFF0);
#pragma unroll
        for (int it = 0; it < 2; ++it) {
            int row = crow + it * 64;
            CP16(bs + row * RSB + cq * 16,
                 wh + (size_t)row * 1024 + kb + cq * 16);
        }
        CP_COMMIT();
    };

    // produce A: fp32 stage -> fp16 rn -> A plane
    auto produceA = [&]() {
#pragma unroll
        for (int it = 0; it < 4; ++it) {
            int row = grow + it * 32;
            float4 va = *(const float4*)(dsm + FPA_OFF + row * FROW + gf4 * 16);
            *(uint2*)(dsm + row * RSB + gf4 * 8) = pack4h(va);
        }
    };

    // prologue: chunk 0
    cp_chunk(0, 0);
    CP_WAIT0();
    produceA();
    __syncthreads();

    for (int c = 0; c < NKCHUNK; ++c) {
        const int s = c & 1;
        if (c + 1 < NKCHUNK) cp_chunk(c + 1, s ^ 1);

        // folded zeroing (independent STG.128, overlaps MMA)
#pragma unroll
        for (int j = 0; j < 3; ++j) {
            int e   = (c * 3 + j) * 256 + tid;
            int f4c = e & 15;
            int row = (e >> 4) & 127;
            int c6  = e >> 11;
            float4* dst = (float4*)out
                + (size_t)(mt * 128 + row) * (IN_F / 4)
                + nz[c6] * (COUT / 4) + zslot * 16 + f4c;
            *dst = make_float4(0.f, 0.f, 0.f, 0.f);
        }

        // ---- MMA: A x B(stage s), chunk c, single pass ----
        const unsigned sa  = smb + (unsigned)(wm * 64) * RSB;
        const unsigned sb_ = smb + (s ? BS_OFF1 : BS_OFF0)
                           + (unsigned)(wn * 32) * RSB;
#pragma unroll
        for (int ks = 0; ks < 2; ++ks) {
            const unsigned ko = (unsigned)ks * 32;
            unsigned ah[4][4], bh[2][4];
#pragma unroll
            for (int mb = 0; mb < 4; ++mb)
                LDSM4(ah[mb][0], ah[mb][1], ah[mb][2], ah[mb][3],
                      sa + (unsigned)(mb * 16) * RSB + ko + a_lane);
#pragma unroll
            for (int nb2 = 0; nb2 < 2; ++nb2)
                LDSM4(bh[nb2][0], bh[nb2][1], bh[nb2][2], bh[nb2][3],
                      sb_ + (unsigned)(nb2 * 16) * RSB + ko + b_lane);
#pragma unroll
            for (int mb = 0; mb < 4; ++mb)
#pragma unroll
                for (int nb = 0; nb < 4; ++nb)
                    MMA16816(acc[mb][nb], ah[mb], &bh[nb >> 1][(nb & 1) * 2]);
        }
        __syncthreads();                  // all warps done with A plane + B(s)

        if (c + 1 < NKCHUNK) {
            CP_WAIT0();                   // chunk c+1 (A fp32 + B fp16) landed
            produceA();                   // A plane := chunk c+1
        }
        __syncthreads();
    }

    // ---- epilogue: bias + scattered store ----
    const int g   = lane >> 2;
    const int tig = lane & 3;
    const float* bg = bias + chunk * COUT + nt * BN + wn * 32;
    float* og = out + (size_t)(mt * BM + wm * 64) * IN_F + chunk * COUT + nt * BN + wn * 32;

#pragma unroll
    for (int mb = 0; mb < 4; ++mb) {
#pragma unroll
        for (int nb = 0; nb < 4; ++nb) {
            int col = nb * 8 + tig * 2;
            float b0 = bg[col], b1 = bg[col + 1];
            int r0 = mb * 16 + g;
            float2 v0 = make_float2(acc[mb][nb][0] + b0, acc[mb][nb][1] + b1);
            float2 v1 = make_float2(acc[mb][nb][2] + b0, acc[mb][nb][3] + b1);
            *(float2*)(og + (size_t)r0 * IN_F + col)       = v0;
            *(float2*)(og + (size_t)(r0 + 8) * IN_F + col) = v1;
        }
    }
}

// ---------------------------------------------------------------------------
extern "C" void kernel_launch(void* const* d_in, const int* in_sizes, int n_in,
                              void* d_out, int out_size) {
    const float* x    = (const float*)d_in[0];
    const float* W    = (const float*)d_in[1];
    const float* bias = (const float*)d_in[2];
    float* out        = (float*)d_out;
    float* out_act    = out + (size_t)BATCH * IN_F;

    cudaFuncSetAttribute(gemm_mma_kernel,
                         cudaFuncAttributeMaxDynamicSharedMemorySize, DSMEM_B);

    dim3 gact(NCHUNK + 1, ACT_YBLK);
    act_fused_kernel<<<gact, 256>>>(x, W, out_act);

    dim3 ggemm(COUT / BN, BATCH / BM, TOPK);
    gemm_mma_kernel<<<ggemm, 256, DSMEM_B>>>(x, bias, out);
}